// round 9
// baseline (speedup 1.0000x reference)
#include <cuda_runtime.h>
#include <mma.h>
#include <cstdint>
#include <cstddef>

using namespace nvcuda;

#define NN   100000
#define EE   1600000
#define DIN  165
#define DMID 82
#define DH   128
#define DG   64

// ---------------- scratch (static device globals) ---------------------------
__device__ float g_t  [NN * DMID];   // relu(x@W1)
__device__ float g_y1 [NN * DIN];    // boosted features
__device__ float g_zl [NN * DH];     // y1 @ sage_wl
__device__ float g_zr [NN * DH];     // y1 @ sage_wr
__device__ float g_x2 [NN * DH];     // SAGE output
__device__ float g_h  [NN * DG];     // GAT projected features
__device__ float g_as [NN];
__device__ float g_ad [NN];
__device__ int   g_cnt [NN];
__device__ int   g_rowptr[NN + 1];
__device__ int   g_cursor[NN];
__device__ int   g_bsum[256];
__device__ int   g_col [EE];

// ---------------- warp reduce helpers ---------------------------------------
__device__ __forceinline__ float wredmax(float v) {
    #pragma unroll
    for (int o = 16; o; o >>= 1) v = fmaxf(v, __shfl_xor_sync(0xffffffffu, v, o));
    return v;
}
__device__ __forceinline__ float wredsum(float v) {
    #pragma unroll
    for (int o = 16; o; o >>= 1) v += __shfl_xor_sync(0xffffffffu, v, o);
    return v;
}

// ---------------- CSR build --------------------------------------------------
__global__ void k_zero_cnt(int n) {
    int i = blockIdx.x * blockDim.x + threadIdx.x;
    if (i < n) g_cnt[i] = 0;
}

__global__ void k_hist(const int* __restrict__ ei, int e, int n) {
    int i = blockIdx.x * blockDim.x + threadIdx.x;
    if (i < e) {
        int d = ei[e + i];
        if ((unsigned)d < (unsigned)n) atomicAdd(&g_cnt[d], 1);
    }
}

__global__ void k_scan1(int n) {
    __shared__ int sh[1024];
    int t = threadIdx.x;
    int i = blockIdx.x * 1024 + t;
    int v = (i < n) ? g_cnt[i] : 0;
    sh[t] = v;
    __syncthreads();
    #pragma unroll
    for (int off = 1; off < 1024; off <<= 1) {
        int x = (t >= off) ? sh[t - off] : 0;
        __syncthreads();
        sh[t] += x;
        __syncthreads();
    }
    int incl = sh[t];
    if (i < n) g_rowptr[i] = incl - v;
    if (t == 1023) g_bsum[blockIdx.x] = incl;
}

__global__ void k_scan2(int nb) {
    __shared__ int sh[256];
    int t = threadIdx.x;
    int v = (t < nb) ? g_bsum[t] : 0;
    sh[t] = v;
    __syncthreads();
    #pragma unroll
    for (int off = 1; off < 256; off <<= 1) {
        int x = (t >= off) ? sh[t - off] : 0;
        __syncthreads();
        sh[t] += x;
        __syncthreads();
    }
    if (t < nb) g_bsum[t] = sh[t] - v;   // exclusive
}

__global__ void k_scan3(int n, int e) {
    int i = blockIdx.x * blockDim.x + threadIdx.x;
    if (i < n) {
        int v = g_rowptr[i] + g_bsum[i >> 10];
        g_rowptr[i] = v;
        g_cursor[i] = v;
    }
    if (i == 0) g_rowptr[n] = e;
}

__global__ void k_fill(const int* __restrict__ ei, int e, int n) {
    int i = blockIdx.x * blockDim.x + threadIdx.x;
    if (i < e) {
        int d = ei[e + i];
        int s = ei[i];
        if ((unsigned)d < (unsigned)n && (unsigned)s < (unsigned)n) {
            int pos = atomicAdd(&g_cursor[d], 1);
            g_col[pos] = s;
        }
    }
}

// ---------------- tf32 wmma GEMM core (64x64 tile, 8 warps, 3xTF32 split) ---
// Result left in sm.out[64][68]; caller epilogues from there.
typedef wmma::fragment<wmma::matrix_a, 16, 16, 8, wmma::precision::tf32, wmma::row_major> FragA;
typedef wmma::fragment<wmma::matrix_b, 16, 16, 8, wmma::precision::tf32, wmma::row_major> FragB;
typedef wmma::fragment<wmma::accumulator, 16, 16, 8, float> FragC;

struct GemmSmem {
    union {
        struct { float a[64][36]; float b[32][68]; } in;
        float out[64][68];
    };
};

template<int K, typename WF>
__device__ __forceinline__ void gemm_wmma(
    const float* __restrict__ A, int n, int rowBase, int tid, WF wfetch,
    GemmSmem& sm)
{
    const int warp = tid >> 5;
    const int wr = warp & 3;        // warp row: 4 x 16 = 64
    const int wc = warp >> 2;       // warp col: 2 x 32 = 64

    FragC acc0, acc1;
    wmma::fill_fragment(acc0, 0.0f);
    wmma::fill_fragment(acc1, 0.0f);

    const int NCH = (K + 31) / 32;
    for (int ch = 0; ch < NCH; ch++) {
        int k0 = ch * 32;
        // fill A tile 64x32 (coalesced global, conflict-free STS)
        #pragma unroll
        for (int i = 0; i < 8; i++) {
            int idx = tid + i * 256;
            int r = idx >> 5, kk = idx & 31;
            int row = rowBase + r, k = k0 + kk;
            sm.in.a[r][kk] = (row < n && k < K) ? A[(size_t)row * K + k] : 0.0f;
        }
        // fill B tile 32x64
        #pragma unroll
        for (int i = 0; i < 8; i++) {
            int idx = tid + i * 256;
            int kk = idx >> 6, c = idx & 63;
            sm.in.b[kk][c] = wfetch(k0 + kk, c);
        }
        __syncthreads();

        #pragma unroll
        for (int ks = 0; ks < 4; ks++) {
            int kb = ks * 8;
            FragA ah, al;
            wmma::load_matrix_sync(ah, &sm.in.a[wr * 16][kb], 36);
            #pragma unroll
            for (int e2 = 0; e2 < ah.num_elements; e2++) {
                float v = ah.x[e2];
                float hi = wmma::__float_to_tf32(v);
                al.x[e2] = wmma::__float_to_tf32(v - hi);
                ah.x[e2] = hi;
            }
            FragB b0h, b0l, b1h, b1l;
            wmma::load_matrix_sync(b0h, &sm.in.b[kb][wc * 32], 68);
            wmma::load_matrix_sync(b1h, &sm.in.b[kb][wc * 32 + 16], 68);
            #pragma unroll
            for (int e2 = 0; e2 < b0h.num_elements; e2++) {
                float v0 = b0h.x[e2], v1 = b1h.x[e2];
                float h0 = wmma::__float_to_tf32(v0), h1 = wmma::__float_to_tf32(v1);
                b0l.x[e2] = wmma::__float_to_tf32(v0 - h0);
                b1l.x[e2] = wmma::__float_to_tf32(v1 - h1);
                b0h.x[e2] = h0; b1h.x[e2] = h1;
            }
            wmma::mma_sync(acc0, ah, b0h, acc0);
            wmma::mma_sync(acc0, al, b0h, acc0);
            wmma::mma_sync(acc0, ah, b0l, acc0);
            wmma::mma_sync(acc1, ah, b1h, acc1);
            wmma::mma_sync(acc1, al, b1h, acc1);
            wmma::mma_sync(acc1, ah, b1l, acc1);
        }
        __syncthreads();
    }
    // stage result in smem for the epilogue
    wmma::store_matrix_sync(&sm.out[wr * 16][wc * 32],      acc0, 68, wmma::mem_row_major);
    wmma::store_matrix_sync(&sm.out[wr * 16][wc * 32 + 16], acc1, 68, wmma::mem_row_major);
    __syncthreads();
}

// FB stage 1: g_t = relu(x @ fb_w1)   M=82 -> grid.x=2
__global__ __launch_bounds__(256) void k_fb1(const float* __restrict__ x,
                                             const float* __restrict__ w1, int n)
{
    __shared__ GemmSmem sm;
    int tid = threadIdx.x;
    int rowBase = blockIdx.y * 64, colBase = blockIdx.x * 64;
    auto wf = [&](int k, int c) -> float {
        int col = colBase + c;
        return (k < DIN && col < DMID) ? w1[(size_t)k * DMID + col] : 0.0f;
    };
    gemm_wmma<DIN>(x, n, rowBase, tid, wf, sm);
    #pragma unroll
    for (int i = 0; i < 16; i++) {
        int idx = tid + i * 256;
        int rl = idx >> 6, cl = idx & 63;
        int r = rowBase + rl, c = colBase + cl;
        if (r < n && c < DMID)
            g_t[(size_t)r * DMID + c] = fmaxf(sm.out[rl][cl], 0.0f);
    }
}

// FB stage 2: g_y1 = x * sigmoid(2 * (g_t @ fb_w2))   M=165 -> grid.x=3
__global__ __launch_bounds__(256) void k_fb2(const float* __restrict__ x,
                                             const float* __restrict__ w2, int n)
{
    __shared__ GemmSmem sm;
    int tid = threadIdx.x;
    int rowBase = blockIdx.y * 64, colBase = blockIdx.x * 64;
    auto wf = [&](int k, int c) -> float {
        int col = colBase + c;
        return (k < DMID && col < DIN) ? w2[(size_t)k * DIN + col] : 0.0f;
    };
    gemm_wmma<DMID>(g_t, n, rowBase, tid, wf, sm);
    #pragma unroll
    for (int i = 0; i < 16; i++) {
        int idx = tid + i * 256;
        int rl = idx >> 6, cl = idx & 63;
        int r = rowBase + rl, c = colBase + cl;
        if (r < n && c < DIN) {
            float sig = 1.0f / (1.0f + __expf(-2.0f * sm.out[rl][cl]));
            g_y1[(size_t)r * DIN + c] = x[(size_t)r * DIN + c] * sig;
        }
    }
}

// SAGE dual GEMM: zl = y1 @ wl, zr = y1 @ wr   grid.x=4
__global__ __launch_bounds__(256) void k_dual(const float* __restrict__ wl,
                                              const float* __restrict__ wr, int n)
{
    __shared__ GemmSmem sm;
    int tid = threadIdx.x;
    int bx = blockIdx.x;
    const float* W   = (bx < 2) ? wl : wr;
    float*       dst = (bx < 2) ? g_zl : g_zr;
    int rowBase = blockIdx.y * 64, colBase = (bx & 1) * 64;
    auto wf = [&](int k, int c) -> float {
        return (k < DIN) ? W[(size_t)k * DH + colBase + c] : 0.0f;
    };
    gemm_wmma<DIN>(g_y1, n, rowBase, tid, wf, sm);
    #pragma unroll
    for (int i = 0; i < 16; i++) {
        int idx = tid + i * 256;
        int rl = idx >> 6, cl = idx & 63;
        int r = rowBase + rl;
        if (r < n) dst[(size_t)r * DH + colBase + cl] = sm.out[rl][cl];
    }
}

// SAGE finalize: x2 = relu(mean_gather(zl) + zr + bl)   (warp per node)
__global__ __launch_bounds__(256) void k_sage_fin(const float* __restrict__ bl, int n)
{
    int w = (blockIdx.x * blockDim.x + threadIdx.x) >> 5;
    int lane = threadIdx.x & 31;
    if (w >= n) return;
    int beg = g_rowptr[w], end = g_rowptr[w + 1];
    float4 acc = make_float4(0.f, 0.f, 0.f, 0.f);
    int e = beg;
    for (; e + 2 <= end; e += 2) {
        const float4* p0 = (const float4*)(g_zl + (size_t)g_col[e]     * DH);
        const float4* p1 = (const float4*)(g_zl + (size_t)g_col[e + 1] * DH);
        float4 a = p0[lane], b = p1[lane];
        acc.x += a.x + b.x; acc.y += a.y + b.y;
        acc.z += a.z + b.z; acc.w += a.w + b.w;
    }
    if (e < end) {
        const float4* p0 = (const float4*)(g_zl + (size_t)g_col[e] * DH);
        float4 a = p0[lane];
        acc.x += a.x; acc.y += a.y; acc.z += a.z; acc.w += a.w;
    }
    float inv = 1.0f / fmaxf((float)(end - beg), 1.0f);
    const float4* zr  = (const float4*)(g_zr + (size_t)w * DH);
    const float4* bl4 = (const float4*)bl;
    float4 z = zr[lane], b4 = bl4[lane];
    float4 o;
    o.x = fmaxf(acc.x * inv + z.x + b4.x, 0.0f);
    o.y = fmaxf(acc.y * inv + z.y + b4.y, 0.0f);
    o.z = fmaxf(acc.z * inv + z.z + b4.z, 0.0f);
    o.w = fmaxf(acc.w * inv + z.w + b4.w, 0.0f);
    ((float4*)(g_x2 + (size_t)w * DH))[lane] = o;
}

// GAT projection + attention logits fused: g_h = x2 @ gat_w; as/ad per row.
__global__ __launch_bounds__(256) void k_gat_h(const float* __restrict__ gw,
                                               const float* __restrict__ att_s,
                                               const float* __restrict__ att_d, int n)
{
    __shared__ GemmSmem sm;
    int tid = threadIdx.x;
    int rowBase = blockIdx.y * 64;
    auto wf = [&](int k, int c) -> float {
        return (c < DG) ? gw[(size_t)k * DG + c] : 0.0f;
    };
    gemm_wmma<DH>(g_x2, n, rowBase, tid, wf, sm);
    // epilogue: 4 threads per row; each handles 16 cols
    int rl = tid >> 2, q = tid & 3;
    int r = rowBase + rl;
    float ps = 0.0f, pd = 0.0f;
    #pragma unroll
    for (int j = 0; j < 16; j++) {
        int c = q * 16 + j;
        float v = sm.out[rl][c];
        if (r < n) g_h[(size_t)r * DG + c] = v;
        ps += v * att_s[c];
        pd += v * att_d[c];
    }
    #pragma unroll
    for (int o = 1; o < 4; o <<= 1) {
        ps += __shfl_xor_sync(0xffffffffu, ps, o);
        pd += __shfl_xor_sync(0xffffffffu, pd, o);
    }
    if (q == 0 && r < n) { g_as[r] = ps; g_ad[r] = pd; }
}

// GAT softmax-aggregate + bias + relu + Cheb(64->1) + sigmoid, fully fused.
__global__ __launch_bounds__(256) void k_gat_agg(const float* __restrict__ gat_b,
                                                 const float* __restrict__ cheb_w,
                                                 const float* __restrict__ cheb_b,
                                                 float* __restrict__ out, int n)
{
    int w = (blockIdx.x * blockDim.x + threadIdx.x) >> 5;
    int lane = threadIdx.x & 31;
    if (w >= n) return;
    int beg = g_rowptr[w], end = g_rowptr[w + 1];
    float ad_i = g_ad[w];
    float es = g_as[w] + ad_i;
    es = es > 0.0f ? es : 0.2f * es;            // self-loop leaky relu
    float m = es;
    for (int base = beg; base < end; base += 32) {
        int j = base + lane;
        float e = -1e30f;
        if (j < end) {
            int s = g_col[j];
            float t = g_as[s] + ad_i;
            e = t > 0.0f ? t : 0.2f * t;
        }
        m = fmaxf(m, e);
    }
    m = wredmax(m);
    float sl = 0.0f, a0 = 0.0f, a1 = 0.0f;
    for (int base = beg; base < end; base += 32) {
        int j = base + lane;
        int s = 0;
        float wgt = 0.0f;
        if (j < end) {
            s = g_col[j];
            float t = g_as[s] + ad_i;
            t = t > 0.0f ? t : 0.2f * t;
            wgt = __expf(t - m);
        }
        sl += wgt;
        int cnt = min(32, end - base);
        for (int jj = 0; jj < cnt; jj++) {
            float wj = __shfl_sync(0xffffffffu, wgt, jj);
            int   sj = __shfl_sync(0xffffffffu, s, jj);
            float2 hv = ((const float2*)(g_h + (size_t)sj * DG))[lane];
            a0 += wj * hv.x;
            a1 += wj * hv.y;
        }
    }
    float ws = __expf(es - m);
    float stot = wredsum(sl) + ws;
    float2 hi = ((const float2*)(g_h + (size_t)w * DG))[lane];
    a0 += ws * hi.x;
    a1 += ws * hi.y;
    float r = 1.0f / (stot + 1e-16f);
    float x0 = fmaxf(a0 * r + gat_b[2 * lane],     0.0f);
    float x1 = fmaxf(a1 * r + gat_b[2 * lane + 1], 0.0f);
    float part = x0 * cheb_w[2 * lane] + x1 * cheb_w[2 * lane + 1];
    part = wredsum(part);
    if (lane == 0) out[w] = 1.0f / (1.0f + __expf(-(part + cheb_b[0])));
}

// ---------------- launch -----------------------------------------------------
extern "C" void kernel_launch(void* const* d_in, const int* in_sizes, int n_in,
                              void* d_out, int out_size)
{
    const float* x       = (const float*)d_in[0];
    const int*   ei      = (const int*)d_in[1];       // int32
    const float* fb_w1   = (const float*)d_in[2];
    const float* fb_w2   = (const float*)d_in[3];
    const float* sage_wl = (const float*)d_in[4];
    const float* sage_bl = (const float*)d_in[5];
    const float* sage_wr = (const float*)d_in[6];
    const float* gat_w   = (const float*)d_in[7];
    const float* att_s   = (const float*)d_in[8];
    const float* att_d   = (const float*)d_in[9];
    const float* gat_b   = (const float*)d_in[10];
    const float* cheb_w  = (const float*)d_in[11];
    const float* cheb_b  = (const float*)d_in[12];
    float*       out     = (float*)d_out;

    int n = in_sizes[0] / DIN;
    int e = in_sizes[1] / 2;

    // CSR build (by dst)
    k_zero_cnt<<<(n + 255) / 256, 256>>>(n);
    k_hist<<<(e + 255) / 256, 256>>>(ei, e, n);
    int nb = (n + 1023) / 1024;
    k_scan1<<<nb, 1024>>>(n);
    k_scan2<<<1, 256>>>(nb);
    k_scan3<<<(n + 255) / 256, 256>>>(n, e);
    k_fill<<<(e + 255) / 256, 256>>>(ei, e, n);

    int rowTiles = (n + 63) / 64;
    // FeatureBooster
    { dim3 g(2, rowTiles); k_fb1<<<g, 256>>>(x, fb_w1, n); }
    { dim3 g(3, rowTiles); k_fb2<<<g, 256>>>(x, fb_w2, n); }
    // SAGE (projected space)
    { dim3 g(4, rowTiles); k_dual<<<g, 256>>>(sage_wl, sage_wr, n); }
    k_sage_fin<<<(n + 7) / 8, 256>>>(sage_bl, n);
    // GAT
    { dim3 g(1, rowTiles); k_gat_h<<<g, 256>>>(gat_w, att_s, att_d, n); }
    k_gat_agg<<<(n + 7) / 8, 256>>>(gat_b, cheb_w, cheb_b, out, n);
}

// round 11
// speedup vs baseline: 1.3795x; 1.3795x over previous
#include <cuda_runtime.h>
#include <cstdint>
#include <cstddef>

#define NN   100000
#define EE   1600000
#define DIN  165
#define DMID 82
#define DH   128
#define DG   64

// ---------------- scratch (static device globals) ---------------------------
__device__ float g_t  [NN * DMID];   // relu(x@W1)
__device__ float g_y1 [NN * DIN];    // boosted features
__device__ float g_zl [NN * DH];     // y1 @ sage_wl
__device__ float g_zr [NN * DH];     // y1 @ sage_wr
__device__ float g_x2 [NN * DH];     // SAGE output
__device__ float g_h  [NN * DG];     // GAT projected features
__device__ float g_as [NN];
__device__ float g_ad [NN];
__device__ int   g_cnt [NN];
__device__ int   g_rowptr[NN + 1];
__device__ int   g_cursor[NN];
__device__ int   g_bsum[256];
__device__ int   g_col [EE];

// ---------------- warp reduce helpers ---------------------------------------
__device__ __forceinline__ float wredmax(float v) {
    #pragma unroll
    for (int o = 16; o; o >>= 1) v = fmaxf(v, __shfl_xor_sync(0xffffffffu, v, o));
    return v;
}
__device__ __forceinline__ float wredsum(float v) {
    #pragma unroll
    for (int o = 16; o; o >>= 1) v += __shfl_xor_sync(0xffffffffu, v, o);
    return v;
}

// ---------------- CSR build --------------------------------------------------
__global__ void k_zero_cnt(int n) {
    int i = blockIdx.x * blockDim.x + threadIdx.x;
    if (i < n) g_cnt[i] = 0;
}

__global__ void k_hist(const int* __restrict__ ei, int e, int n) {
    int i = blockIdx.x * blockDim.x + threadIdx.x;
    if (i < e) {
        int d = ei[e + i];
        if ((unsigned)d < (unsigned)n) atomicAdd(&g_cnt[d], 1);
    }
}

__global__ void k_scan1(int n) {
    __shared__ int sh[1024];
    int t = threadIdx.x;
    int i = blockIdx.x * 1024 + t;
    int v = (i < n) ? g_cnt[i] : 0;
    sh[t] = v;
    __syncthreads();
    #pragma unroll
    for (int off = 1; off < 1024; off <<= 1) {
        int x = (t >= off) ? sh[t - off] : 0;
        __syncthreads();
        sh[t] += x;
        __syncthreads();
    }
    int incl = sh[t];
    if (i < n) g_rowptr[i] = incl - v;
    if (t == 1023) g_bsum[blockIdx.x] = incl;
}

__global__ void k_scan2(int nb) {
    __shared__ int sh[256];
    int t = threadIdx.x;
    int v = (t < nb) ? g_bsum[t] : 0;
    sh[t] = v;
    __syncthreads();
    #pragma unroll
    for (int off = 1; off < 256; off <<= 1) {
        int x = (t >= off) ? sh[t - off] : 0;
        __syncthreads();
        sh[t] += x;
        __syncthreads();
    }
    if (t < nb) g_bsum[t] = sh[t] - v;   // exclusive
}

__global__ void k_scan3(int n, int e) {
    int i = blockIdx.x * blockDim.x + threadIdx.x;
    if (i < n) {
        int v = g_rowptr[i] + g_bsum[i >> 10];
        g_rowptr[i] = v;
        g_cursor[i] = v;
    }
    if (i == 0) g_rowptr[n] = e;
}

__global__ void k_fill(const int* __restrict__ ei, int e, int n) {
    int i = blockIdx.x * blockDim.x + threadIdx.x;
    if (i < e) {
        int d = ei[e + i];
        int s = ei[i];
        if ((unsigned)d < (unsigned)n && (unsigned)s < (unsigned)n) {
            int pos = atomicAdd(&g_cursor[d], 1);
            g_col[pos] = s;
        }
    }
}

// ---------------- tiled SGEMM core (64x64 tile, 4x4 microtile, 256 thr) -----
// Register-staged pipeline: chunk ch+1's LDGs are issued before computing
// chunk ch, so global latency hides under the FFMA phase.
template<int K, int M>
__device__ __forceinline__ void gemm_tile(
    const float* __restrict__ A, const float* __restrict__ W,
    int n, int rowBase, int colBase, int tid,
    float (*sA)[33], float (*sW)[64], float (&acc)[4][4])
{
    const int tx = tid & 15, ty = tid >> 4;
    const int NCH = (K + 31) / 32;

    float ra[8], rb[8];
    // prologue: fetch chunk 0
    #pragma unroll
    for (int i = 0; i < 8; i++) {
        int idx = tid + i * 256;
        int r = idx >> 5, kk = idx & 31;
        int row = rowBase + r;
        ra[i] = (row < n && kk < K) ? A[(size_t)row * K + kk] : 0.0f;
    }
    #pragma unroll
    for (int i = 0; i < 8; i++) {
        int idx = tid + i * 256;
        int kk = idx >> 6, c = idx & 63;
        int col = colBase + c;
        rb[i] = (kk < K && col < M) ? W[(size_t)kk * M + col] : 0.0f;
    }

    for (int ch = 0; ch < NCH; ch++) {
        // commit staged regs to smem
        #pragma unroll
        for (int i = 0; i < 8; i++) {
            int idx = tid + i * 256;
            sA[idx >> 5][idx & 31] = ra[i];
        }
        #pragma unroll
        for (int i = 0; i < 8; i++) {
            int idx = tid + i * 256;
            sW[idx >> 6][idx & 63] = rb[i];
        }
        __syncthreads();

        // prefetch next chunk (LDGs in flight during compute below)
        if (ch + 1 < NCH) {
            int k0 = (ch + 1) * 32;
            #pragma unroll
            for (int i = 0; i < 8; i++) {
                int idx = tid + i * 256;
                int r = idx >> 5, kk = idx & 31;
                int row = rowBase + r, k = k0 + kk;
                ra[i] = (row < n && k < K) ? A[(size_t)row * K + k] : 0.0f;
            }
            #pragma unroll
            for (int i = 0; i < 8; i++) {
                int idx = tid + i * 256;
                int kk = idx >> 6, c = idx & 63;
                int k = k0 + kk, col = colBase + c;
                rb[i] = (k < K && col < M) ? W[(size_t)k * M + col] : 0.0f;
            }
        }

        #pragma unroll
        for (int kk = 0; kk < 32; kk++) {
            float4 b = *(const float4*)&sW[kk][tx * 4];
            float a0 = sA[ty * 4 + 0][kk];
            float a1 = sA[ty * 4 + 1][kk];
            float a2 = sA[ty * 4 + 2][kk];
            float a3 = sA[ty * 4 + 3][kk];
            acc[0][0] += a0 * b.x; acc[0][1] += a0 * b.y; acc[0][2] += a0 * b.z; acc[0][3] += a0 * b.w;
            acc[1][0] += a1 * b.x; acc[1][1] += a1 * b.y; acc[1][2] += a1 * b.z; acc[1][3] += a1 * b.w;
            acc[2][0] += a2 * b.x; acc[2][1] += a2 * b.y; acc[2][2] += a2 * b.z; acc[2][3] += a2 * b.w;
            acc[3][0] += a3 * b.x; acc[3][1] += a3 * b.y; acc[3][2] += a3 * b.z; acc[3][3] += a3 * b.w;
        }
        __syncthreads();
    }
}

// FB stage 1: g_t = relu(x @ fb_w1)
__global__ __launch_bounds__(256) void k_fb1(const float* __restrict__ x,
                                             const float* __restrict__ w1, int n)
{
    __shared__ float sA[64][33];
    __shared__ float sW[32][64];
    float acc[4][4] = {};
    int tid = threadIdx.x;
    int rowBase = blockIdx.y * 64, colBase = blockIdx.x * 64;
    gemm_tile<DIN, DMID>(x, w1, n, rowBase, colBase, tid, sA, sW, acc);
    int tx = tid & 15, ty = tid >> 4;
    #pragma unroll
    for (int i = 0; i < 4; i++) {
        int r = rowBase + ty * 4 + i;
        if (r >= n) continue;
        #pragma unroll
        for (int j = 0; j < 4; j++) {
            int c = colBase + tx * 4 + j;
            if (c < DMID) g_t[(size_t)r * DMID + c] = fmaxf(acc[i][j], 0.0f);
        }
    }
}

// FB stage 2: g_y1 = x * sigmoid(2 * (g_t @ fb_w2))
__global__ __launch_bounds__(256) void k_fb2(const float* __restrict__ x,
                                             const float* __restrict__ w2, int n)
{
    __shared__ float sA[64][33];
    __shared__ float sW[32][64];
    float acc[4][4] = {};
    int tid = threadIdx.x;
    int rowBase = blockIdx.y * 64, colBase = blockIdx.x * 64;
    gemm_tile<DMID, DIN>(g_t, w2, n, rowBase, colBase, tid, sA, sW, acc);
    int tx = tid & 15, ty = tid >> 4;
    #pragma unroll
    for (int i = 0; i < 4; i++) {
        int r = rowBase + ty * 4 + i;
        if (r >= n) continue;
        #pragma unroll
        for (int j = 0; j < 4; j++) {
            int c = colBase + tx * 4 + j;
            if (c < DIN) {
                float sig = 1.0f / (1.0f + __expf(-2.0f * acc[i][j]));
                g_y1[(size_t)r * DIN + c] = x[(size_t)r * DIN + c] * sig;
            }
        }
    }
}

// SAGE dual GEMM: zl = y1 @ wl, zr = y1 @ wr  (4 col tiles: 0,1->wl; 2,3->wr)
__global__ __launch_bounds__(256) void k_dual(const float* __restrict__ wl,
                                              const float* __restrict__ wr, int n)
{
    __shared__ float sA[64][33];
    __shared__ float sW[32][64];
    float acc[4][4] = {};
    int tid = threadIdx.x;
    int bx = blockIdx.x;
    const float* W   = (bx < 2) ? wl : wr;
    float*       dst = (bx < 2) ? g_zl : g_zr;
    int rowBase = blockIdx.y * 64, colBase = (bx & 1) * 64;
    gemm_tile<DIN, DH>(g_y1, W, n, rowBase, colBase, tid, sA, sW, acc);
    int tx = tid & 15, ty = tid >> 4;
    #pragma unroll
    for (int i = 0; i < 4; i++) {
        int r = rowBase + ty * 4 + i;
        if (r >= n) continue;
        #pragma unroll
        for (int j = 0; j < 4; j++) {
            int c = colBase + tx * 4 + j;
            dst[(size_t)r * DH + c] = acc[i][j];
        }
    }
}

// SAGE finalize: x2 = relu(mean_gather(zl) + zr + bl)   (warp per node)
__global__ __launch_bounds__(256) void k_sage_fin(const float* __restrict__ bl, int n)
{
    int w = (blockIdx.x * blockDim.x + threadIdx.x) >> 5;
    int lane = threadIdx.x & 31;
    if (w >= n) return;
    int beg = g_rowptr[w], end = g_rowptr[w + 1];
    float4 acc = make_float4(0.f, 0.f, 0.f, 0.f);
    int e = beg;
    for (; e + 2 <= end; e += 2) {
        const float4* p0 = (const float4*)(g_zl + (size_t)g_col[e]     * DH);
        const float4* p1 = (const float4*)(g_zl + (size_t)g_col[e + 1] * DH);
        float4 a = p0[lane], b = p1[lane];
        acc.x += a.x + b.x; acc.y += a.y + b.y;
        acc.z += a.z + b.z; acc.w += a.w + b.w;
    }
    if (e < end) {
        const float4* p0 = (const float4*)(g_zl + (size_t)g_col[e] * DH);
        float4 a = p0[lane];
        acc.x += a.x; acc.y += a.y; acc.z += a.z; acc.w += a.w;
    }
    float inv = 1.0f / fmaxf((float)(end - beg), 1.0f);
    const float4* zr  = (const float4*)(g_zr + (size_t)w * DH);
    const float4* bl4 = (const float4*)bl;
    float4 z = zr[lane], b4 = bl4[lane];
    float4 o;
    o.x = fmaxf(acc.x * inv + z.x + b4.x, 0.0f);
    o.y = fmaxf(acc.y * inv + z.y + b4.y, 0.0f);
    o.z = fmaxf(acc.z * inv + z.z + b4.z, 0.0f);
    o.w = fmaxf(acc.w * inv + z.w + b4.w, 0.0f);
    ((float4*)(g_x2 + (size_t)w * DH))[lane] = o;
}

// GAT projection + attention logits fused: g_h = x2 @ gat_w; as/ad per row.
__global__ __launch_bounds__(256) void k_gat_h(const float* __restrict__ gw,
                                               const float* __restrict__ att_s,
                                               const float* __restrict__ att_d, int n)
{
    __shared__ float sA[64][33];
    __shared__ float sW[32][64];
    float acc[4][4] = {};
    int tid = threadIdx.x;
    int rowBase = blockIdx.y * 64;
    gemm_tile<DH, DG>(g_x2, gw, n, rowBase, 0, tid, sA, sW, acc);
    int tx = tid & 15, ty = tid >> 4;
    #pragma unroll
    for (int i = 0; i < 4; i++) {
        int r = rowBase + ty * 4 + i;
        float ps = 0.0f, pd = 0.0f;
        #pragma unroll
        for (int j = 0; j < 4; j++) {
            int c = tx * 4 + j;
            if (r < n) g_h[(size_t)r * DG + c] = acc[i][j];
            ps += acc[i][j] * att_s[c];
            pd += acc[i][j] * att_d[c];
        }
        // reduce across the 16 tx lanes of this half-warp
        #pragma unroll
        for (int o = 8; o; o >>= 1) {
            ps += __shfl_xor_sync(0xffffffffu, ps, o);
            pd += __shfl_xor_sync(0xffffffffu, pd, o);
        }
        if (tx == 0 && r < n) { g_as[r] = ps; g_ad[r] = pd; }
    }
}

// GAT softmax-aggregate + bias + relu + Cheb(64->1) + sigmoid, fully fused.
__global__ __launch_bounds__(256) void k_gat_agg(const float* __restrict__ gat_b,
                                                 const float* __restrict__ cheb_w,
                                                 const float* __restrict__ cheb_b,
                                                 float* __restrict__ out, int n)
{
    int w = (blockIdx.x * blockDim.x + threadIdx.x) >> 5;
    int lane = threadIdx.x & 31;
    if (w >= n) return;
    int beg = g_rowptr[w], end = g_rowptr[w + 1];
    float ad_i = g_ad[w];
    float es = g_as[w] + ad_i;
    es = es > 0.0f ? es : 0.2f * es;            // self-loop leaky relu
    float m = es;
    for (int base = beg; base < end; base += 32) {
        int j = base + lane;
        float e = -1e30f;
        if (j < end) {
            int s = g_col[j];
            float t = g_as[s] + ad_i;
            e = t > 0.0f ? t : 0.2f * t;
        }
        m = fmaxf(m, e);
    }
    m = wredmax(m);
    float sl = 0.0f, a0 = 0.0f, a1 = 0.0f;
    for (int base = beg; base < end; base += 32) {
        int j = base + lane;
        int s = 0;
        float wgt = 0.0f;
        if (j < end) {
            s = g_col[j];
            float t = g_as[s] + ad_i;
            t = t > 0.0f ? t : 0.2f * t;
            wgt = __expf(t - m);
        }
        sl += wgt;
        int cnt = min(32, end - base);
        for (int jj = 0; jj < cnt; jj++) {
            float wj = __shfl_sync(0xffffffffu, wgt, jj);
            int   sj = __shfl_sync(0xffffffffu, s, jj);
            float2 hv = ((const float2*)(g_h + (size_t)sj * DG))[lane];
            a0 += wj * hv.x;
            a1 += wj * hv.y;
        }
    }
    float ws = __expf(es - m);
    float stot = wredsum(sl) + ws;
    float2 hi = ((const float2*)(g_h + (size_t)w * DG))[lane];
    a0 += ws * hi.x;
    a1 += ws * hi.y;
    float r = 1.0f / (stot + 1e-16f);
    float x0 = fmaxf(a0 * r + gat_b[2 * lane],     0.0f);
    float x1 = fmaxf(a1 * r + gat_b[2 * lane + 1], 0.0f);
    float part = x0 * cheb_w[2 * lane] + x1 * cheb_w[2 * lane + 1];
    part = wredsum(part);
    if (lane == 0) out[w] = 1.0f / (1.0f + __expf(-(part + cheb_b[0])));
}

// ---------------- launch -----------------------------------------------------
extern "C" void kernel_launch(void* const* d_in, const int* in_sizes, int n_in,
                              void* d_out, int out_size)
{
    const float* x       = (const float*)d_in[0];
    const int*   ei      = (const int*)d_in[1];       // int32
    const float* fb_w1   = (const float*)d_in[2];
    const float* fb_w2   = (const float*)d_in[3];
    const float* sage_wl = (const float*)d_in[4];
    const float* sage_bl = (const float*)d_in[5];
    const float* sage_wr = (const float*)d_in[6];
    const float* gat_w   = (const float*)d_in[7];
    const float* att_s   = (const float*)d_in[8];
    const float* att_d   = (const float*)d_in[9];
    const float* gat_b   = (const float*)d_in[10];
    const float* cheb_w  = (const float*)d_in[11];
    const float* cheb_b  = (const float*)d_in[12];
    float*       out     = (float*)d_out;

    int n = in_sizes[0] / DIN;
    int e = in_sizes[1] / 2;

    // CSR build (by dst) — serialized on the main stream
    k_zero_cnt<<<(n + 255) / 256, 256>>>(n);
    k_hist<<<(e + 255) / 256, 256>>>(ei, e, n);
    int nb = (n + 1023) / 1024;
    k_scan1<<<nb, 1024>>>(n);
    k_scan2<<<1, 256>>>(nb);
    k_scan3<<<(n + 255) / 256, 256>>>(n, e);
    k_fill<<<(e + 255) / 256, 256>>>(ei, e, n);

    int rowTiles = (n + 63) / 64;
    // FeatureBooster
    { dim3 g(2, rowTiles); k_fb1<<<g, 256>>>(x, fb_w1, n); }
    { dim3 g(3, rowTiles); k_fb2<<<g, 256>>>(x, fb_w2, n); }
    // SAGE (projected space)
    { dim3 g(4, rowTiles); k_dual<<<g, 256>>>(sage_wl, sage_wr, n); }
    k_sage_fin<<<(n + 7) / 8, 256>>>(sage_bl, n);
    // GAT
    { dim3 g(1, rowTiles); k_gat_h<<<g, 256>>>(gat_w, att_s, att_d, n); }
    k_gat_agg<<<(n + 7) / 8, 256>>>(gat_b, cheb_w, cheb_b, out, n);
}

// round 14
// speedup vs baseline: 1.5540x; 1.1266x over previous
#include <cuda_runtime.h>
#include <cstdint>
#include <cstddef>

#define NN   100000
#define EE   1600000
#define DIN  165
#define DMID 82
#define DH   128
#define DG   64

// ---------------- scratch (static device globals) ---------------------------
__device__ float g_t  [NN * DMID];   // relu(x@W1)
__device__ float g_y1 [NN * DIN];    // boosted features
__device__ float g_zl [NN * DH];     // y1 @ sage_wl
__device__ float g_zr [NN * DH];     // y1 @ sage_wr
__device__ float g_x2 [NN * DH];     // SAGE output
__device__ float g_h  [NN * DG];     // GAT projected features
__device__ float g_as [NN];
__device__ float g_ad [NN];
__device__ int   g_cnt [NN];
__device__ int   g_rowptr[NN + 1];
__device__ int   g_cursor[NN];
__device__ int   g_bsum[256];
__device__ int   g_col [EE];

// ---------------- warp reduce helpers ---------------------------------------
__device__ __forceinline__ float wredmax(float v) {
    #pragma unroll
    for (int o = 16; o; o >>= 1) v = fmaxf(v, __shfl_xor_sync(0xffffffffu, v, o));
    return v;
}
__device__ __forceinline__ float wredsum(float v) {
    #pragma unroll
    for (int o = 16; o; o >>= 1) v += __shfl_xor_sync(0xffffffffu, v, o);
    return v;
}

// ---------------- CSR build --------------------------------------------------
__global__ void k_zero_cnt(int n) {
    int i = blockIdx.x * blockDim.x + threadIdx.x;
    if (i < n) g_cnt[i] = 0;
}

__global__ void k_hist(const int* __restrict__ ei, int e, int n) {
    int i = blockIdx.x * blockDim.x + threadIdx.x;
    if (i < e) {
        int d = ei[e + i];
        if ((unsigned)d < (unsigned)n) atomicAdd(&g_cnt[d], 1);
    }
}

__global__ void k_scan1(int n) {
    __shared__ int sh[1024];
    int t = threadIdx.x;
    int i = blockIdx.x * 1024 + t;
    int v = (i < n) ? g_cnt[i] : 0;
    sh[t] = v;
    __syncthreads();
    #pragma unroll
    for (int off = 1; off < 1024; off <<= 1) {
        int x = (t >= off) ? sh[t - off] : 0;
        __syncthreads();
        sh[t] += x;
        __syncthreads();
    }
    int incl = sh[t];
    if (i < n) g_rowptr[i] = incl - v;
    if (t == 1023) g_bsum[blockIdx.x] = incl;
}

__global__ void k_scan2(int nb) {
    __shared__ int sh[256];
    int t = threadIdx.x;
    int v = (t < nb) ? g_bsum[t] : 0;
    sh[t] = v;
    __syncthreads();
    #pragma unroll
    for (int off = 1; off < 256; off <<= 1) {
        int x = (t >= off) ? sh[t - off] : 0;
        __syncthreads();
        sh[t] += x;
        __syncthreads();
    }
    if (t < nb) g_bsum[t] = sh[t] - v;   // exclusive
}

__global__ void k_scan3(int n, int e) {
    int i = blockIdx.x * blockDim.x + threadIdx.x;
    if (i < n) {
        int v = g_rowptr[i] + g_bsum[i >> 10];
        g_rowptr[i] = v;
        g_cursor[i] = v;
    }
    if (i == 0) g_rowptr[n] = e;
}

__global__ void k_fill(const int* __restrict__ ei, int e, int n) {
    int i = blockIdx.x * blockDim.x + threadIdx.x;
    if (i < e) {
        int d = ei[e + i];
        int s = ei[i];
        if ((unsigned)d < (unsigned)n && (unsigned)s < (unsigned)n) {
            int pos = atomicAdd(&g_cursor[d], 1);
            g_col[pos] = s;
        }
    }
}

// ---------------- tiled SGEMM core (64x64 tile, 4x4 microtile, 256 thr) -----
// Full 32-wide K chunks (no k-guards) + one short templated tail chunk, so
// padded-K FFMA waste disappears without touching the proven inner loop.
template<int K, int M>
__device__ __forceinline__ void gemm_tile(
    const float* __restrict__ A, const float* __restrict__ W,
    int n, int rowBase, int colBase, int tid,
    float (*sA)[33], float (*sW)[64], float (&acc)[4][4])
{
    const int tx = tid & 15, ty = tid >> 4;
    constexpr int NFULL = K / 32;
    constexpr int TAIL  = K % 32;

    #pragma unroll 1
    for (int ch = 0; ch < NFULL; ch++) {
        int k0 = ch * 32;
        #pragma unroll
        for (int i = 0; i < 8; i++) {
            int idx = tid + i * 256;
            int r = idx >> 5, kk = idx & 31;
            int row = rowBase + r;
            sA[r][kk] = (row < n) ? A[(size_t)row * K + k0 + kk] : 0.0f;
        }
        #pragma unroll
        for (int i = 0; i < 8; i++) {
            int idx = tid + i * 256;
            int kk = idx >> 6, c = idx & 63;
            int col = colBase + c;
            sW[kk][c] = (col < M) ? W[(size_t)(k0 + kk) * M + col] : 0.0f;
        }
        __syncthreads();
        #pragma unroll
        for (int kk = 0; kk < 32; kk++) {
            float4 b = *(const float4*)&sW[kk][tx * 4];
            float a0 = sA[ty * 4 + 0][kk];
            float a1 = sA[ty * 4 + 1][kk];
            float a2 = sA[ty * 4 + 2][kk];
            float a3 = sA[ty * 4 + 3][kk];
            acc[0][0] += a0 * b.x; acc[0][1] += a0 * b.y; acc[0][2] += a0 * b.z; acc[0][3] += a0 * b.w;
            acc[1][0] += a1 * b.x; acc[1][1] += a1 * b.y; acc[1][2] += a1 * b.z; acc[1][3] += a1 * b.w;
            acc[2][0] += a2 * b.x; acc[2][1] += a2 * b.y; acc[2][2] += a2 * b.z; acc[2][3] += a2 * b.w;
            acc[3][0] += a3 * b.x; acc[3][1] += a3 * b.y; acc[3][2] += a3 * b.z; acc[3][3] += a3 * b.w;
        }
        __syncthreads();
    }

    if constexpr (TAIL > 0) {
        constexpr int k0 = NFULL * 32;
        for (int idx = tid; idx < 64 * TAIL; idx += 256) {
            int r = idx / TAIL, kk = idx % TAIL;    // const division -> mul/shift
            int row = rowBase + r;
            sA[r][kk] = (row < n) ? A[(size_t)row * K + k0 + kk] : 0.0f;
        }
        for (int idx = tid; idx < TAIL * 64; idx += 256) {
            int kk = idx >> 6, c = idx & 63;
            int col = colBase + c;
            sW[kk][c] = (col < M) ? W[(size_t)(k0 + kk) * M + col] : 0.0f;
        }
        __syncthreads();
        #pragma unroll
        for (int kk = 0; kk < TAIL; kk++) {
            float4 b = *(const float4*)&sW[kk][tx * 4];
            float a0 = sA[ty * 4 + 0][kk];
            float a1 = sA[ty * 4 + 1][kk];
            float a2 = sA[ty * 4 + 2][kk];
            float a3 = sA[ty * 4 + 3][kk];
            acc[0][0] += a0 * b.x; acc[0][1] += a0 * b.y; acc[0][2] += a0 * b.z; acc[0][3] += a0 * b.w;
            acc[1][0] += a1 * b.x; acc[1][1] += a1 * b.y; acc[1][2] += a1 * b.z; acc[1][3] += a1 * b.w;
            acc[2][0] += a2 * b.x; acc[2][1] += a2 * b.y; acc[2][2] += a2 * b.z; acc[2][3] += a2 * b.w;
            acc[3][0] += a3 * b.x; acc[3][1] += a3 * b.y; acc[3][2] += a3 * b.z; acc[3][3] += a3 * b.w;
        }
        __syncthreads();
    }
}

// FB stage 1: g_t = relu(x @ fb_w1)
__global__ __launch_bounds__(256) void k_fb1(const float* __restrict__ x,
                                             const float* __restrict__ w1, int n)
{
    __shared__ float sA[64][33];
    __shared__ float sW[32][64];
    float acc[4][4] = {};
    int tid = threadIdx.x;
    int rowBase = blockIdx.y * 64, colBase = blockIdx.x * 64;
    gemm_tile<DIN, DMID>(x, w1, n, rowBase, colBase, tid, sA, sW, acc);
    int tx = tid & 15, ty = tid >> 4;
    #pragma unroll
    for (int i = 0; i < 4; i++) {
        int r = rowBase + ty * 4 + i;
        if (r >= n) continue;
        #pragma unroll
        for (int j = 0; j < 4; j++) {
            int c = colBase + tx * 4 + j;
            if (c < DMID) g_t[(size_t)r * DMID + c] = fmaxf(acc[i][j], 0.0f);
        }
    }
}

// FB stage 2: g_y1 = x * sigmoid(2 * (g_t @ fb_w2))
__global__ __launch_bounds__(256) void k_fb2(const float* __restrict__ x,
                                             const float* __restrict__ w2, int n)
{
    __shared__ float sA[64][33];
    __shared__ float sW[32][64];
    float acc[4][4] = {};
    int tid = threadIdx.x;
    int rowBase = blockIdx.y * 64, colBase = blockIdx.x * 64;
    gemm_tile<DMID, DIN>(g_t, w2, n, rowBase, colBase, tid, sA, sW, acc);
    int tx = tid & 15, ty = tid >> 4;
    #pragma unroll
    for (int i = 0; i < 4; i++) {
        int r = rowBase + ty * 4 + i;
        if (r >= n) continue;
        #pragma unroll
        for (int j = 0; j < 4; j++) {
            int c = colBase + tx * 4 + j;
            if (c < DIN) {
                float sig = 1.0f / (1.0f + __expf(-2.0f * acc[i][j]));
                g_y1[(size_t)r * DIN + c] = x[(size_t)r * DIN + c] * sig;
            }
        }
    }
}

// SAGE dual GEMM: zl = y1 @ wl, zr = y1 @ wr  (4 col tiles: 0,1->wl; 2,3->wr)
__global__ __launch_bounds__(256) void k_dual(const float* __restrict__ wl,
                                              const float* __restrict__ wr, int n)
{
    __shared__ float sA[64][33];
    __shared__ float sW[32][64];
    float acc[4][4] = {};
    int tid = threadIdx.x;
    int bx = blockIdx.x;
    const float* W   = (bx < 2) ? wl : wr;
    float*       dst = (bx < 2) ? g_zl : g_zr;
    int rowBase = blockIdx.y * 64, colBase = (bx & 1) * 64;
    gemm_tile<DIN, DH>(g_y1, W, n, rowBase, colBase, tid, sA, sW, acc);
    int tx = tid & 15, ty = tid >> 4;
    #pragma unroll
    for (int i = 0; i < 4; i++) {
        int r = rowBase + ty * 4 + i;
        if (r >= n) continue;
        #pragma unroll
        for (int j = 0; j < 4; j++) {
            int c = colBase + tx * 4 + j;
            dst[(size_t)r * DH + c] = acc[i][j];
        }
    }
}

// SAGE finalize: x2 = relu(mean_gather(zl) + zr + bl)   (warp per node)
__global__ __launch_bounds__(256) void k_sage_fin(const float* __restrict__ bl, int n)
{
    int w = (blockIdx.x * blockDim.x + threadIdx.x) >> 5;
    int lane = threadIdx.x & 31;
    if (w >= n) return;
    int beg = g_rowptr[w], end = g_rowptr[w + 1];
    float4 acc = make_float4(0.f, 0.f, 0.f, 0.f);
    int e = beg;
    for (; e + 2 <= end; e += 2) {
        const float4* p0 = (const float4*)(g_zl + (size_t)g_col[e]     * DH);
        const float4* p1 = (const float4*)(g_zl + (size_t)g_col[e + 1] * DH);
        float4 a = p0[lane], b = p1[lane];
        acc.x += a.x + b.x; acc.y += a.y + b.y;
        acc.z += a.z + b.z; acc.w += a.w + b.w;
    }
    if (e < end) {
        const float4* p0 = (const float4*)(g_zl + (size_t)g_col[e] * DH);
        float4 a = p0[lane];
        acc.x += a.x; acc.y += a.y; acc.z += a.z; acc.w += a.w;
    }
    float inv = 1.0f / fmaxf((float)(end - beg), 1.0f);
    const float4* zr  = (const float4*)(g_zr + (size_t)w * DH);
    const float4* bl4 = (const float4*)bl;
    float4 z = zr[lane], b4 = bl4[lane];
    float4 o;
    o.x = fmaxf(acc.x * inv + z.x + b4.x, 0.0f);
    o.y = fmaxf(acc.y * inv + z.y + b4.y, 0.0f);
    o.z = fmaxf(acc.z * inv + z.z + b4.z, 0.0f);
    o.w = fmaxf(acc.w * inv + z.w + b4.w, 0.0f);
    ((float4*)(g_x2 + (size_t)w * DH))[lane] = o;
}

// GAT projection + attention logits fused: g_h = x2 @ gat_w; as/ad per row.
__global__ __launch_bounds__(256) void k_gat_h(const float* __restrict__ gw,
                                               const float* __restrict__ att_s,
                                               const float* __restrict__ att_d, int n)
{
    __shared__ float sA[64][33];
    __shared__ float sW[32][64];
    float acc[4][4] = {};
    int tid = threadIdx.x;
    int rowBase = blockIdx.y * 64;
    gemm_tile<DH, DG>(g_x2, gw, n, rowBase, 0, tid, sA, sW, acc);
    int tx = tid & 15, ty = tid >> 4;
    #pragma unroll
    for (int i = 0; i < 4; i++) {
        int r = rowBase + ty * 4 + i;
        float ps = 0.0f, pd = 0.0f;
        #pragma unroll
        for (int j = 0; j < 4; j++) {
            int c = tx * 4 + j;
            if (r < n) g_h[(size_t)r * DG + c] = acc[i][j];
            ps += acc[i][j] * att_s[c];
            pd += acc[i][j] * att_d[c];
        }
        // reduce across the 16 tx lanes of this half-warp
        #pragma unroll
        for (int o = 8; o; o >>= 1) {
            ps += __shfl_xor_sync(0xffffffffu, ps, o);
            pd += __shfl_xor_sync(0xffffffffu, pd, o);
        }
        if (tx == 0 && r < n) { g_as[r] = ps; g_ad[r] = pd; }
    }
}

// GAT softmax-aggregate + bias + relu + Cheb(64->1) + sigmoid, fully fused.
__global__ __launch_bounds__(256) void k_gat_agg(const float* __restrict__ gat_b,
                                                 const float* __restrict__ cheb_w,
                                                 const float* __restrict__ cheb_b,
                                                 float* __restrict__ out, int n)
{
    int w = (blockIdx.x * blockDim.x + threadIdx.x) >> 5;
    int lane = threadIdx.x & 31;
    if (w >= n) return;
    int beg = g_rowptr[w], end = g_rowptr[w + 1];
    float ad_i = g_ad[w];
    float es = g_as[w] + ad_i;
    es = es > 0.0f ? es : 0.2f * es;            // self-loop leaky relu
    float m = es;
    for (int base = beg; base < end; base += 32) {
        int j = base + lane;
        float e = -1e30f;
        if (j < end) {
            int s = g_col[j];
            float t = g_as[s] + ad_i;
            e = t > 0.0f ? t : 0.2f * t;
        }
        m = fmaxf(m, e);
    }
    m = wredmax(m);
    float sl = 0.0f, a0 = 0.0f, a1 = 0.0f;
    for (int base = beg; base < end; base += 32) {
        int j = base + lane;
        int s = 0;
        float wgt = 0.0f;
        if (j < end) {
            s = g_col[j];
            float t = g_as[s] + ad_i;
            t = t > 0.0f ? t : 0.2f * t;
            wgt = __expf(t - m);
        }
        sl += wgt;
        int cnt = min(32, end - base);
        for (int jj = 0; jj < cnt; jj++) {
            float wj = __shfl_sync(0xffffffffu, wgt, jj);
            int   sj = __shfl_sync(0xffffffffu, s, jj);
            float2 hv = ((const float2*)(g_h + (size_t)sj * DG))[lane];
            a0 += wj * hv.x;
            a1 += wj * hv.y;
        }
    }
    float ws = __expf(es - m);
    float stot = wredsum(sl) + ws;
    float2 hi = ((const float2*)(g_h + (size_t)w * DG))[lane];
    a0 += ws * hi.x;
    a1 += ws * hi.y;
    float r = 1.0f / (stot + 1e-16f);
    float x0 = fmaxf(a0 * r + gat_b[2 * lane],     0.0f);
    float x1 = fmaxf(a1 * r + gat_b[2 * lane + 1], 0.0f);
    float part = x0 * cheb_w[2 * lane] + x1 * cheb_w[2 * lane + 1];
    part = wredsum(part);
    if (lane == 0) out[w] = 1.0f / (1.0f + __expf(-(part + cheb_b[0])));
}

// ---------------- launch -----------------------------------------------------
extern "C" void kernel_launch(void* const* d_in, const int* in_sizes, int n_in,
                              void* d_out, int out_size)
{
    const float* x       = (const float*)d_in[0];
    const int*   ei      = (const int*)d_in[1];       // int32
    const float* fb_w1   = (const float*)d_in[2];
    const float* fb_w2   = (const float*)d_in[3];
    const float* sage_wl = (const float*)d_in[4];
    const float* sage_bl = (const float*)d_in[5];
    const float* sage_wr = (const float*)d_in[6];
    const float* gat_w   = (const float*)d_in[7];
    const float* att_s   = (const float*)d_in[8];
    const float* att_d   = (const float*)d_in[9];
    const float* gat_b   = (const float*)d_in[10];
    const float* cheb_w  = (const float*)d_in[11];
    const float* cheb_b  = (const float*)d_in[12];
    float*       out     = (float*)d_out;

    int n = in_sizes[0] / DIN;
    int e = in_sizes[1] / 2;

    // side stream + events for the CSR branch (host objects, created once;
    // the captured graph embeds the fork/join as parallel branches)
    static cudaStream_t s2 = nullptr;
    static cudaEvent_t ev0 = nullptr, ev1 = nullptr;
    if (!s2) {
        cudaStreamCreateWithFlags(&s2, cudaStreamNonBlocking);
        cudaEventCreateWithFlags(&ev0, cudaEventDisableTiming);
        cudaEventCreateWithFlags(&ev1, cudaEventDisableTiming);
    }

    // fork: CSR build on s2, concurrent with the FB/SAGE GEMM chain
    cudaEventRecord(ev0, 0);
    cudaStreamWaitEvent(s2, ev0, 0);
    k_zero_cnt<<<(n + 255) / 256, 256, 0, s2>>>(n);
    k_hist<<<(e + 255) / 256, 256, 0, s2>>>(ei, e, n);
    int nb = (n + 1023) / 1024;
    k_scan1<<<nb, 1024, 0, s2>>>(n);
    k_scan2<<<1, 256, 0, s2>>>(nb);
    k_scan3<<<(n + 255) / 256, 256, 0, s2>>>(n, e);
    k_fill<<<(e + 255) / 256, 256, 0, s2>>>(ei, e, n);
    cudaEventRecord(ev1, s2);

    int rowTiles = (n + 63) / 64;
    // FeatureBooster
    { dim3 g(2, rowTiles); k_fb1<<<g, 256>>>(x, fb_w1, n); }
    { dim3 g(3, rowTiles); k_fb2<<<g, 256>>>(x, fb_w2, n); }
    // SAGE (projected space)
    { dim3 g(4, rowTiles); k_dual<<<g, 256>>>(sage_wl, sage_wr, n); }

    // join: gathers need the CSR
    cudaStreamWaitEvent(0, ev1, 0);
    k_sage_fin<<<(n + 7) / 8, 256>>>(sage_bl, n);
    // GAT
    { dim3 g(1, rowTiles); k_gat_h<<<g, 256>>>(gat_w, att_s, att_d, n); }
    k_gat_agg<<<(n + 7) / 8, 256>>>(gat_b, cheb_w, cheb_b, out, n);
}

// round 16
// speedup vs baseline: 1.6123x; 1.0375x over previous
#include <cuda_runtime.h>
#include <cstdint>
#include <cstddef>

#define NN   100000
#define EE   1600000
#define DIN  165
#define DMID 82
#define DH   128
#define DG   64

// ---------------- scratch (static device globals) ---------------------------
__device__ float g_t  [NN * DMID];   // relu(x@W1)
__device__ float g_y1 [NN * DIN];    // boosted features
__device__ float g_zl [NN * DH];     // y1 @ sage_wl
__device__ float g_zr [NN * DH];     // y1 @ sage_wr
__device__ float g_x2 [NN * DH];     // SAGE output
__device__ float g_h  [NN * DG];     // GAT projected features
__device__ float g_as [NN];
__device__ float g_ad [NN];
__device__ int   g_cnt [NN];
__device__ int   g_rowptr[NN + 1];
__device__ int   g_cursor[NN];
__device__ int   g_bsum[256];
__device__ int   g_col [EE];

// ---------------- warp reduce helpers ---------------------------------------
__device__ __forceinline__ float wredmax(float v) {
    #pragma unroll
    for (int o = 16; o; o >>= 1) v = fmaxf(v, __shfl_xor_sync(0xffffffffu, v, o));
    return v;
}
__device__ __forceinline__ float wredsum(float v) {
    #pragma unroll
    for (int o = 16; o; o >>= 1) v += __shfl_xor_sync(0xffffffffu, v, o);
    return v;
}

// ---------------- CSR build --------------------------------------------------
__global__ void k_zero_cnt(int n) {
    int i = blockIdx.x * blockDim.x + threadIdx.x;
    if (i < n) g_cnt[i] = 0;
}

__global__ void k_hist(const int* __restrict__ ei, int e, int n) {
    int i = blockIdx.x * blockDim.x + threadIdx.x;
    if (i < e) {
        int d = ei[e + i];
        if ((unsigned)d < (unsigned)n) atomicAdd(&g_cnt[d], 1);
    }
}

__global__ void k_scan1(int n) {
    __shared__ int sh[1024];
    int t = threadIdx.x;
    int i = blockIdx.x * 1024 + t;
    int v = (i < n) ? g_cnt[i] : 0;
    sh[t] = v;
    __syncthreads();
    #pragma unroll
    for (int off = 1; off < 1024; off <<= 1) {
        int x = (t >= off) ? sh[t - off] : 0;
        __syncthreads();
        sh[t] += x;
        __syncthreads();
    }
    int incl = sh[t];
    if (i < n) g_rowptr[i] = incl - v;
    if (t == 1023) g_bsum[blockIdx.x] = incl;
}

__global__ void k_scan2(int nb) {
    __shared__ int sh[256];
    int t = threadIdx.x;
    int v = (t < nb) ? g_bsum[t] : 0;
    sh[t] = v;
    __syncthreads();
    #pragma unroll
    for (int off = 1; off < 256; off <<= 1) {
        int x = (t >= off) ? sh[t - off] : 0;
        __syncthreads();
        sh[t] += x;
        __syncthreads();
    }
    if (t < nb) g_bsum[t] = sh[t] - v;   // exclusive
}

__global__ void k_scan3(int n, int e) {
    int i = blockIdx.x * blockDim.x + threadIdx.x;
    if (i < n) {
        int v = g_rowptr[i] + g_bsum[i >> 10];
        g_rowptr[i] = v;
        g_cursor[i] = v;
    }
    if (i == 0) g_rowptr[n] = e;
}

__global__ void k_fill(const int* __restrict__ ei, int e, int n) {
    int i = blockIdx.x * blockDim.x + threadIdx.x;
    if (i < e) {
        int d = ei[e + i];
        int s = ei[i];
        if ((unsigned)d < (unsigned)n && (unsigned)s < (unsigned)n) {
            int pos = atomicAdd(&g_cursor[d], 1);
            g_col[pos] = s;
        }
    }
}

// ---------------- tiled SGEMM core: 64 rows x (NT*64) cols, 256 thr ---------
// Exact-K: full 32-chunks without k-guards + templated short tail.
// NT=2 doubles FMA per A-byte: 4 A-LDS + NT W-LDS.128 + NT*16 FFMA per kk.
template<int K, int M, int NT>
__device__ __forceinline__ void gemm_tile(
    const float* __restrict__ A, const float* __restrict__ W,
    int n, int rowBase, int colBase, int tid,
    float (*sA)[33], float* sW, float (&acc)[NT][4][4])
{
    const int tx = tid & 15, ty = tid >> 4;
    constexpr int NFULL = K / 32;
    constexpr int TAIL  = K % 32;
    constexpr int WROW  = 64 * NT;

    #pragma unroll 1
    for (int ch = 0; ch < NFULL; ch++) {
        int k0 = ch * 32;
        #pragma unroll
        for (int i = 0; i < 8; i++) {
            int idx = tid + i * 256;
            int r = idx >> 5, kk = idx & 31;
            int row = rowBase + r;
            sA[r][kk] = (row < n) ? A[(size_t)row * K + k0 + kk] : 0.0f;
        }
        #pragma unroll
        for (int i = 0; i < 8 * NT; i++) {
            int idx = tid + i * 256;
            int kk = idx / WROW, c = idx % WROW;
            int col = colBase + c;
            sW[kk * WROW + c] = (col < M) ? W[(size_t)(k0 + kk) * M + col] : 0.0f;
        }
        __syncthreads();
        #pragma unroll
        for (int kk = 0; kk < 32; kk++) {
            float a0 = sA[ty * 4 + 0][kk];
            float a1 = sA[ty * 4 + 1][kk];
            float a2 = sA[ty * 4 + 2][kk];
            float a3 = sA[ty * 4 + 3][kk];
            #pragma unroll
            for (int t = 0; t < NT; t++) {
                float4 b = *(const float4*)&sW[kk * WROW + t * 64 + tx * 4];
                acc[t][0][0] += a0 * b.x; acc[t][0][1] += a0 * b.y; acc[t][0][2] += a0 * b.z; acc[t][0][3] += a0 * b.w;
                acc[t][1][0] += a1 * b.x; acc[t][1][1] += a1 * b.y; acc[t][1][2] += a1 * b.z; acc[t][1][3] += a1 * b.w;
                acc[t][2][0] += a2 * b.x; acc[t][2][1] += a2 * b.y; acc[t][2][2] += a2 * b.z; acc[t][2][3] += a2 * b.w;
                acc[t][3][0] += a3 * b.x; acc[t][3][1] += a3 * b.y; acc[t][3][2] += a3 * b.z; acc[t][3][3] += a3 * b.w;
            }
        }
        __syncthreads();
    }

    if constexpr (TAIL > 0) {
        constexpr int k0 = NFULL * 32;
        for (int idx = tid; idx < 64 * TAIL; idx += 256) {
            int r = idx / TAIL, kk = idx % TAIL;
            int row = rowBase + r;
            sA[r][kk] = (row < n) ? A[(size_t)row * K + k0 + kk] : 0.0f;
        }
        for (int idx = tid; idx < TAIL * WROW; idx += 256) {
            int kk = idx / WROW, c = idx % WROW;
            int col = colBase + c;
            sW[kk * WROW + c] = (col < M) ? W[(size_t)(k0 + kk) * M + col] : 0.0f;
        }
        __syncthreads();
        #pragma unroll
        for (int kk = 0; kk < TAIL; kk++) {
            float a0 = sA[ty * 4 + 0][kk];
            float a1 = sA[ty * 4 + 1][kk];
            float a2 = sA[ty * 4 + 2][kk];
            float a3 = sA[ty * 4 + 3][kk];
            #pragma unroll
            for (int t = 0; t < NT; t++) {
                float4 b = *(const float4*)&sW[kk * WROW + t * 64 + tx * 4];
                acc[t][0][0] += a0 * b.x; acc[t][0][1] += a0 * b.y; acc[t][0][2] += a0 * b.z; acc[t][0][3] += a0 * b.w;
                acc[t][1][0] += a1 * b.x; acc[t][1][1] += a1 * b.y; acc[t][1][2] += a1 * b.z; acc[t][1][3] += a1 * b.w;
                acc[t][2][0] += a2 * b.x; acc[t][2][1] += a2 * b.y; acc[t][2][2] += a2 * b.z; acc[t][2][3] += a2 * b.w;
                acc[t][3][0] += a3 * b.x; acc[t][3][1] += a3 * b.y; acc[t][3][2] += a3 * b.z; acc[t][3][3] += a3 * b.w;
            }
        }
        __syncthreads();
    }
}

// FB stage 1: g_t = relu(x @ fb_w1)   NT=2 covers cols 0..127 (82 valid)
__global__ __launch_bounds__(256) void k_fb1(const float* __restrict__ x,
                                             const float* __restrict__ w1, int n)
{
    __shared__ float sA[64][33];
    __shared__ float sW[32 * 128];
    float acc[2][4][4] = {};
    int tid = threadIdx.x;
    int rowBase = blockIdx.y * 64;
    gemm_tile<DIN, DMID, 2>(x, w1, n, rowBase, 0, tid, sA, sW, acc);
    int tx = tid & 15, ty = tid >> 4;
    #pragma unroll
    for (int t = 0; t < 2; t++)
    #pragma unroll
    for (int i = 0; i < 4; i++) {
        int r = rowBase + ty * 4 + i;
        if (r >= n) continue;
        #pragma unroll
        for (int j = 0; j < 4; j++) {
            int c = t * 64 + tx * 4 + j;
            if (c < DMID) g_t[(size_t)r * DMID + c] = fmaxf(acc[t][i][j], 0.0f);
        }
    }
}

// FB stage 2: g_y1 = x * sigmoid(2 * (g_t @ fb_w2))
// bx=0: NT=2 cols 0..127;  bx=1: NT=1 cols 128..164
__global__ __launch_bounds__(256) void k_fb2(const float* __restrict__ x,
                                             const float* __restrict__ w2, int n)
{
    __shared__ float sA[64][33];
    __shared__ float sW[32 * 128];
    int tid = threadIdx.x;
    int rowBase = blockIdx.y * 64;
    int tx = tid & 15, ty = tid >> 4;
    if (blockIdx.x == 0) {
        float acc[2][4][4] = {};
        gemm_tile<DMID, DIN, 2>(g_t, w2, n, rowBase, 0, tid, sA, sW, acc);
        #pragma unroll
        for (int t = 0; t < 2; t++)
        #pragma unroll
        for (int i = 0; i < 4; i++) {
            int r = rowBase + ty * 4 + i;
            if (r >= n) continue;
            #pragma unroll
            for (int j = 0; j < 4; j++) {
                int c = t * 64 + tx * 4 + j;
                float sig = 1.0f / (1.0f + __expf(-2.0f * acc[t][i][j]));
                g_y1[(size_t)r * DIN + c] = x[(size_t)r * DIN + c] * sig;
            }
        }
    } else {
        float acc[1][4][4] = {};
        gemm_tile<DMID, DIN, 1>(g_t, w2, n, rowBase, 128, tid, sA, sW, acc);
        #pragma unroll
        for (int i = 0; i < 4; i++) {
            int r = rowBase + ty * 4 + i;
            if (r >= n) continue;
            #pragma unroll
            for (int j = 0; j < 4; j++) {
                int c = 128 + tx * 4 + j;
                if (c < DIN) {
                    float sig = 1.0f / (1.0f + __expf(-2.0f * acc[0][i][j]));
                    g_y1[(size_t)r * DIN + c] = x[(size_t)r * DIN + c] * sig;
                }
            }
        }
    }
}

// SAGE dual GEMM: bx=0: zl = y1 @ wl;  bx=1: zr = y1 @ wr   (NT=2, full DH)
__global__ __launch_bounds__(256) void k_dual(const float* __restrict__ wl,
                                              const float* __restrict__ wr, int n)
{
    __shared__ float sA[64][33];
    __shared__ float sW[32 * 128];
    float acc[2][4][4] = {};
    int tid = threadIdx.x;
    const float* W   = (blockIdx.x == 0) ? wl : wr;
    float*       dst = (blockIdx.x == 0) ? g_zl : g_zr;
    int rowBase = blockIdx.y * 64;
    gemm_tile<DIN, DH, 2>(g_y1, W, n, rowBase, 0, tid, sA, sW, acc);
    int tx = tid & 15, ty = tid >> 4;
    #pragma unroll
    for (int t = 0; t < 2; t++)
    #pragma unroll
    for (int i = 0; i < 4; i++) {
        int r = rowBase + ty * 4 + i;
        if (r >= n) continue;
        #pragma unroll
        for (int j = 0; j < 4; j++) {
            int c = t * 64 + tx * 4 + j;
            dst[(size_t)r * DH + c] = acc[t][i][j];
        }
    }
}

// SAGE finalize: x2 = relu(mean_gather(zl) + zr + bl)   (warp per node)
__global__ __launch_bounds__(256) void k_sage_fin(const float* __restrict__ bl, int n)
{
    int w = (blockIdx.x * blockDim.x + threadIdx.x) >> 5;
    int lane = threadIdx.x & 31;
    if (w >= n) return;
    int beg = g_rowptr[w], end = g_rowptr[w + 1];
    float4 acc = make_float4(0.f, 0.f, 0.f, 0.f);
    int e = beg;
    for (; e + 2 <= end; e += 2) {
        const float4* p0 = (const float4*)(g_zl + (size_t)g_col[e]     * DH);
        const float4* p1 = (const float4*)(g_zl + (size_t)g_col[e + 1] * DH);
        float4 a = p0[lane], b = p1[lane];
        acc.x += a.x + b.x; acc.y += a.y + b.y;
        acc.z += a.z + b.z; acc.w += a.w + b.w;
    }
    if (e < end) {
        const float4* p0 = (const float4*)(g_zl + (size_t)g_col[e] * DH);
        float4 a = p0[lane];
        acc.x += a.x; acc.y += a.y; acc.z += a.z; acc.w += a.w;
    }
    float inv = 1.0f / fmaxf((float)(end - beg), 1.0f);
    const float4* zr  = (const float4*)(g_zr + (size_t)w * DH);
    const float4* bl4 = (const float4*)bl;
    float4 z = zr[lane], b4 = bl4[lane];
    float4 o;
    o.x = fmaxf(acc.x * inv + z.x + b4.x, 0.0f);
    o.y = fmaxf(acc.y * inv + z.y + b4.y, 0.0f);
    o.z = fmaxf(acc.z * inv + z.z + b4.z, 0.0f);
    o.w = fmaxf(acc.w * inv + z.w + b4.w, 0.0f);
    ((float4*)(g_x2 + (size_t)w * DH))[lane] = o;
}

// GAT projection + attention logits fused: g_h = x2 @ gat_w; as/ad per row.
__global__ __launch_bounds__(256) void k_gat_h(const float* __restrict__ gw,
                                               const float* __restrict__ att_s,
                                               const float* __restrict__ att_d, int n)
{
    __shared__ float sA[64][33];
    __shared__ float sW[32 * 64];
    float acc[1][4][4] = {};
    int tid = threadIdx.x;
    int rowBase = blockIdx.y * 64;
    gemm_tile<DH, DG, 1>(g_x2, gw, n, rowBase, 0, tid, sA, sW, acc);
    int tx = tid & 15, ty = tid >> 4;
    #pragma unroll
    for (int i = 0; i < 4; i++) {
        int r = rowBase + ty * 4 + i;
        float ps = 0.0f, pd = 0.0f;
        #pragma unroll
        for (int j = 0; j < 4; j++) {
            int c = tx * 4 + j;
            if (r < n) g_h[(size_t)r * DG + c] = acc[0][i][j];
            ps += acc[0][i][j] * att_s[c];
            pd += acc[0][i][j] * att_d[c];
        }
        #pragma unroll
        for (int o = 8; o; o >>= 1) {
            ps += __shfl_xor_sync(0xffffffffu, ps, o);
            pd += __shfl_xor_sync(0xffffffffu, pd, o);
        }
        if (tx == 0 && r < n) { g_as[r] = ps; g_ad[r] = pd; }
    }
}

// GAT softmax-aggregate + bias + relu + Cheb(64->1) + sigmoid, fully fused.
__global__ __launch_bounds__(256) void k_gat_agg(const float* __restrict__ gat_b,
                                                 const float* __restrict__ cheb_w,
                                                 const float* __restrict__ cheb_b,
                                                 float* __restrict__ out, int n)
{
    int w = (blockIdx.x * blockDim.x + threadIdx.x) >> 5;
    int lane = threadIdx.x & 31;
    if (w >= n) return;
    int beg = g_rowptr[w], end = g_rowptr[w + 1];
    float ad_i = g_ad[w];
    float es = g_as[w] + ad_i;
    es = es > 0.0f ? es : 0.2f * es;            // self-loop leaky relu
    float m = es;
    for (int base = beg; base < end; base += 32) {
        int j = base + lane;
        float e = -1e30f;
        if (j < end) {
            int s = g_col[j];
            float t = g_as[s] + ad_i;
            e = t > 0.0f ? t : 0.2f * t;
        }
        m = fmaxf(m, e);
    }
    m = wredmax(m);
    float sl = 0.0f, a0 = 0.0f, a1 = 0.0f;
    for (int base = beg; base < end; base += 32) {
        int j = base + lane;
        int s = 0;
        float wgt = 0.0f;
        if (j < end) {
            s = g_col[j];
            float t = g_as[s] + ad_i;
            t = t > 0.0f ? t : 0.2f * t;
            wgt = __expf(t - m);
        }
        sl += wgt;
        int cnt = min(32, end - base);
        for (int jj = 0; jj < cnt; jj++) {
            float wj = __shfl_sync(0xffffffffu, wgt, jj);
            int   sj = __shfl_sync(0xffffffffu, s, jj);
            float2 hv = ((const float2*)(g_h + (size_t)sj * DG))[lane];
            a0 += wj * hv.x;
            a1 += wj * hv.y;
        }
    }
    float ws = __expf(es - m);
    float stot = wredsum(sl) + ws;
    float2 hi = ((const float2*)(g_h + (size_t)w * DG))[lane];
    a0 += ws * hi.x;
    a1 += ws * hi.y;
    float r = 1.0f / (stot + 1e-16f);
    float x0 = fmaxf(a0 * r + gat_b[2 * lane],     0.0f);
    float x1 = fmaxf(a1 * r + gat_b[2 * lane + 1], 0.0f);
    float part = x0 * cheb_w[2 * lane] + x1 * cheb_w[2 * lane + 1];
    part = wredsum(part);
    if (lane == 0) out[w] = 1.0f / (1.0f + __expf(-(part + cheb_b[0])));
}

// ---------------- launch -----------------------------------------------------
extern "C" void kernel_launch(void* const* d_in, const int* in_sizes, int n_in,
                              void* d_out, int out_size)
{
    const float* x       = (const float*)d_in[0];
    const int*   ei      = (const int*)d_in[1];       // int32
    const float* fb_w1   = (const float*)d_in[2];
    const float* fb_w2   = (const float*)d_in[3];
    const float* sage_wl = (const float*)d_in[4];
    const float* sage_bl = (const float*)d_in[5];
    const float* sage_wr = (const float*)d_in[6];
    const float* gat_w   = (const float*)d_in[7];
    const float* att_s   = (const float*)d_in[8];
    const float* att_d   = (const float*)d_in[9];
    const float* gat_b   = (const float*)d_in[10];
    const float* cheb_w  = (const float*)d_in[11];
    const float* cheb_b  = (const float*)d_in[12];
    float*       out     = (float*)d_out;

    int n = in_sizes[0] / DIN;
    int e = in_sizes[1] / 2;

    // side stream + events for the CSR branch
    static cudaStream_t s2 = nullptr;
    static cudaEvent_t ev0 = nullptr, ev1 = nullptr;
    if (!s2) {
        cudaStreamCreateWithFlags(&s2, cudaStreamNonBlocking);
        cudaEventCreateWithFlags(&ev0, cudaEventDisableTiming);
        cudaEventCreateWithFlags(&ev1, cudaEventDisableTiming);
    }

    // fork: CSR build on s2, concurrent with the FB/SAGE GEMM chain
    cudaEventRecord(ev0, 0);
    cudaStreamWaitEvent(s2, ev0, 0);
    k_zero_cnt<<<(n + 255) / 256, 256, 0, s2>>>(n);
    k_hist<<<(e + 255) / 256, 256, 0, s2>>>(ei, e, n);
    int nb = (n + 1023) / 1024;
    k_scan1<<<nb, 1024, 0, s2>>>(n);
    k_scan2<<<1, 256, 0, s2>>>(nb);
    k_scan3<<<(n + 255) / 256, 256, 0, s2>>>(n, e);
    k_fill<<<(e + 255) / 256, 256, 0, s2>>>(ei, e, n);
    cudaEventRecord(ev1, s2);

    int rowTiles = (n + 63) / 64;
    // FeatureBooster
    { dim3 g(1, rowTiles); k_fb1<<<g, 256>>>(x, fb_w1, n); }
    { dim3 g(2, rowTiles); k_fb2<<<g, 256>>>(x, fb_w2, n); }
    // SAGE (projected space)
    { dim3 g(2, rowTiles); k_dual<<<g, 256>>>(sage_wl, sage_wr, n); }

    // join: gathers need the CSR
    cudaStreamWaitEvent(0, ev1, 0);
    k_sage_fin<<<(n + 7) / 8, 256>>>(sage_bl, n);
    // GAT
    { dim3 g(1, rowTiles); k_gat_h<<<g, 256>>>(gat_w, att_s, att_d, n); }
    k_gat_agg<<<(n + 7) / 8, 256>>>(gat_b, cheb_w, cheb_b, out, n);
}